// round 5
// baseline (speedup 1.0000x reference)
#include <cuda_runtime.h>
#include <cuda_bf16.h>

// CTC forward: one block (128 threads = 4 warps) per batch element.
// Thread i owns pair (E_i = state 2i, O_i = state 2i+1) in registers.
// Skewed warp pipeline: warp w runs K steps behind warp w-1.
//   - intra-warp neighbor O via __shfl_up_sync (no smem, no barrier)
//   - cross-warp boundary O values exchanged K-at-a-time through a tiny
//     double-buffered smem array; ONE __syncthreads per K steps.
// Alphas in log2 domain (emissions pre-scaled by log2 e).

#define NEGF  (-1e30f)
#define LOG2E 1.4426950408889634f
#define LN2   0.6931471805599453f
#define MAXB  1024
#define KW    8

__device__ float        g_per_ex[MAXB];
__device__ unsigned int g_count = 0;

__device__ __forceinline__ float lse2(float a, float b) {
    float m = fmaxf(a, b);
    float d = fminf(a, b) - m;          // <= 0
    return m + __log2f(1.0f + exp2f(d));
}

__global__ __launch_bounds__(128, 1)
void ctc_forward_kernel(const float* __restrict__ pred,           // (B, T, C)
                        const int*   __restrict__ targets,        // (B, L)
                        const int*   __restrict__ pred_lengths,   // (B,)
                        const int*   __restrict__ target_lengths, // (B,)
                        float*       __restrict__ out,
                        int T, int C, int L, int B)
{
    // boundary ring: [phase parity][producer warp 0..2][slot 0..K]
    // slot 0 = O at window start (time v*K), slot k+1 = O at time v*K+1+k
    __shared__ float sB[2][3][KW + 1];
    __shared__ float sOf[128];
    __shared__ float sEf[129];
    __shared__ unsigned int s_last;
    __shared__ float sred[4];

    const int b    = blockIdx.x;
    const int i    = threadIdx.x;        // pair index 0..127
    const int w    = i >> 5;
    const int lane = i & 31;

    const int  li   = (i < L) ? i : (L - 1);
    const int  lbl  = targets[(size_t)b * L + li];
    const int  prev = (li >= 1) ? targets[(size_t)b * L + li - 1] : -1;
    const bool skip = (lbl != 0) && (lbl != prev);

    const float* rowp = pred + (size_t)b * T * C;

    int pl = pred_lengths[b];
    int Teff = pl < T ? pl : T; if (Teff < 1) Teff = 1;
    const int steps = Teff - 1;                 // updates at t = 1..steps
    const int W = (steps + KW - 1) / KW;        // number of K-step windows

    // ---- init (t = 0) ----
    float eb0 = __ldg(rowp) * LOG2E;
    float el0 = __ldg(rowp + lbl) * LOG2E;
    float E  = (i == 0) ? eb0 : NEGF;    // state 2i
    float O  = (i == 0) ? el0 : NEGF;    // state 2i+1
    float E2 = NEGF;                     // state 2L (thread 127 only)

    // prime emissions for window 0 (t = 1..K, clamped)
    float eb[KW], el[KW];
#pragma unroll
    for (int k = 0; k < KW; k++) {
        int tt = 1 + k; if (tt > steps) tt = steps; if (tt < 0) tt = 0;
        const float* p = rowp + (size_t)tt * C;
        eb[k] = __ldg(p) * LOG2E;
        el[k] = __ldg(p + lbl) * LOG2E;
    }

    const int totalPhases = W + 3;        // warp w handles window v at phase v+w
    for (int ph = 0; ph < totalPhases; ph++) {
        __syncthreads();                  // makes previous phase's sB writes visible
        const int v = ph - w;             // this warp's window index this phase
        if (v >= 0 && v < W) {
            const int cur = ph & 1, prv = cur ^ 1;
            const int tbase = v * KW;     // steps t = tbase+1 .. tbase+K

            // publish boundary O at window start (time tbase)
            if (w < 3 && lane == 31) sB[cur][w][0] = O;

            // fetch the K boundary values this window needs (times tbase..tbase+K-1)
            float bnd[KW];
            if (lane == 0 && w > 0) {
#pragma unroll
                for (int k = 0; k < KW; k++) bnd[k] = sB[prv][w - 1][k];
            } else {
#pragma unroll
                for (int k = 0; k < KW; k++) bnd[k] = NEGF;
            }

            const bool pf = (v + 1 < W);  // prefetch next window's emissions
#pragma unroll
            for (int k = 0; k < KW; k++) {
                const int t = tbase + 1 + k;
                if (t <= steps) {                       // warp-uniform
                    float sh  = __shfl_up_sync(0xffffffffu, O, 1);
                    float Om1 = (lane == 0) ? bnd[k] : sh;

                    if (i == 127) E2 = lse2(E2, O) + eb[k];   // own O (old)

                    float m1   = fmaxf(O, E);
                    float Om1s = skip ? Om1 : NEGF;
                    float mO   = fmaxf(m1, Om1s);
                    float s3   = exp2f(O - mO) + exp2f(E - mO) + exp2f(Om1s - mO);
                    float nO   = mO + __log2f(s3) + el[k];
                    float nE   = lse2(E, Om1) + eb[k];

                    if (w < 3 && lane == 31) sB[cur][w][k + 1] = nO;
                    O = nO; E = nE;
                }
                if (pf) {                               // rotate emissions in place
                    int tn = tbase + KW + 1 + k; if (tn > steps) tn = steps;
                    const float* p = rowp + (size_t)tn * C;
                    eb[k] = __ldg(p) * LOG2E;
                    el[k] = __ldg(p + lbl) * LOG2E;
                }
            }
        }
    }
    __syncthreads();

    // ---- gather + per-example loss ----
    sOf[i] = O;                  // O_i
    sEf[i] = E;                  // E_i
    if (i == 127) sEf[128] = E2; // E_128 (only meaningful when L == 128)
    __syncthreads();

    if (i == 0) {
        int tl = target_lengths[b];
        int tlc = tl; if (tlc < 1) tlc = 1; if (tlc > L) tlc = L;
        float l1 = sOf[tlc - 1];        // state 2*tl - 1
        float l2 = sEf[tlc];            // state 2*tl
        float per = -(lse2(l1, l2) * LN2);
        if (per > 1e29f) per = 0.0f;
        int denom = tl < 1 ? 1 : tl;
        g_per_ex[b] = per / (float)denom;
        __threadfence();
        unsigned prevc = atomicAdd(&g_count, 1u);
        s_last = (prevc == (unsigned)(B - 1)) ? 1u : 0u;
    }
    __syncthreads();

    // ---- last block computes the batch mean (deterministic fixed order) ----
    if (s_last) {
        float v = 0.f;
        for (int idx = i; idx < B; idx += 128)
            v += *((volatile float*)&g_per_ex[idx]);
#pragma unroll
        for (int o = 16; o > 0; o >>= 1)
            v += __shfl_down_sync(0xffffffffu, v, o);
        if (lane == 0) sred[w] = v;
        __syncthreads();
        if (i == 0) {
            float tot = sred[0] + sred[1] + sred[2] + sred[3];
            out[0] = tot / (float)B;
            g_count = 0;    // reset for next graph replay
        }
    }
}

extern "C" void kernel_launch(void* const* d_in, const int* in_sizes, int n_in,
                              void* d_out, int out_size)
{
    const float* pred           = (const float*)d_in[0];
    const int*   targets        = (const int*)d_in[1];
    const int*   pred_lengths   = (const int*)d_in[2];
    const int*   target_lengths = (const int*)d_in[3];

    const int B = in_sizes[2];
    const int L = in_sizes[1] / B;
    const int C = 128;
    const int T = (in_sizes[0] / B) / C;

    ctc_forward_kernel<<<B, 128>>>(pred, targets, pred_lengths, target_lengths,
                                   (float*)d_out, T, C, L, B);
}

// round 6
// speedup vs baseline: 3.6137x; 3.6137x over previous
#include <cuda_runtime.h>
#include <cuda_bf16.h>

// CTC forward: one block (128 threads = 4 warps) per batch element.
// Thread i owns pair (E_i = state 2i, O_i = state 2i+1) in registers.
// TWO time steps per __syncthreads via halo: thread i redundantly recomputes
// O_{i-1}(t) from {O_{i-1},E_{i-1},O_{i-2}}(t-1), so the barrier runs at half
// rate. Alphas in log2 domain; lse uses raw MUFU ex2/lg2.approx.

#define NEGF  (-1e30f)
#define LOG2E 1.4426950408889634f
#define LN2   0.6931471805599453f
#define MAXB  1024

__device__ float        g_per_ex[MAXB];
__device__ unsigned int g_count = 0;

__device__ __forceinline__ float ex2(float x) { float r; asm("ex2.approx.f32 %0, %1;" : "=f"(r) : "f"(x)); return r; }
__device__ __forceinline__ float lg2(float x) { float r; asm("lg2.approx.f32 %0, %1;" : "=f"(r) : "f"(x)); return r; }

__device__ __forceinline__ float lse2(float a, float b) {
    float m = fmaxf(a, b);
    float d = fminf(a, b) - m;          // <= 0
    return m + lg2(1.0f + ex2(d));
}
__device__ __forceinline__ float lse3(float a, float b, float c) {
    float m = fmaxf(fmaxf(a, b), c);
    return m + lg2(ex2(a - m) + ex2(b - m) + ex2(c - m));
}

__global__ __launch_bounds__(128, 1)
void ctc_forward_kernel(const float* __restrict__ pred,           // (B, T, C)
                        const int*   __restrict__ targets,        // (B, L)
                        const int*   __restrict__ pred_lengths,   // (B,)
                        const int*   __restrict__ target_lengths, // (B,)
                        float*       __restrict__ out,
                        int T, int C, int L, int B)
{
    // (E_i, O_i) stored at [i+2]; [0] and [1] are (NEG,NEG) sentinels.
    __shared__ float2 sEO[2][131];
    __shared__ float sOf[128];
    __shared__ float sEf[129];
    __shared__ unsigned int s_last;
    __shared__ float sred[4];

    const int b    = blockIdx.x;
    const int i    = threadIdx.x;        // pair index 0..127
    const int w    = i >> 5;
    const int lane = i & 31;

    const int  li    = (i < L) ? i : (L - 1);
    const int  lbl   = targets[(size_t)b * L + li];
    const int  lblm1 = (li >= 1) ? targets[(size_t)b * L + li - 1] : -1;
    const int  lblm2 = (li >= 2) ? targets[(size_t)b * L + li - 2] : -1;
    const bool skip   = (lbl != 0) && (lbl != lblm1);
    const bool skipm1 = (li >= 1) && (lblm1 != 0) && (lblm1 != lblm2);
    const int  colm1  = (li >= 1) ? lblm1 : 0;    // neighbor's emission column

    const float* rowp = pred + (size_t)b * T * C;

    int pl = pred_lengths[b];
    int Teff = pl < T ? pl : T; if (Teff < 1) Teff = 1;
    const int steps = Teff - 1;          // updates at t = 1..steps

    // ---- init (t = 0) ----
    float eb0 = __ldg(rowp) * LOG2E;
    float el0 = __ldg(rowp + lbl) * LOG2E;
    float E  = (i == 0) ? eb0 : NEGF;    // state 2i
    float O  = (i == 0) ? el0 : NEGF;    // state 2i+1
    float E2 = NEGF;                     // state 2L (thread 127 only)

    if (i < 2) { sEO[0][i] = make_float2(NEGF, NEGF); sEO[1][i] = make_float2(NEGF, NEGF); }
    sEO[0][i + 2] = make_float2(E, O);

    // emission rings, depth 8 (blank, own label, neighbor label)
    float eb[8], el[8], em[8];
#pragma unroll
    for (int j = 0; j < 8; j++) {
        int tt = 1 + j; if (tt > steps) tt = steps; if (tt < 0) tt = 0;
        const float* p = rowp + (size_t)tt * C;
        eb[j] = __ldg(p) * LOG2E;
        el[j] = __ldg(p + lbl) * LOG2E;
        em[j] = __ldg(p + colm1) * LOG2E;
    }

    __syncthreads();

    int t = 1;
    // ---- main loop: 4 two-step rounds per iteration (8 steps) ----
    for (; t + 7 <= steps; t += 8) {
#pragma unroll
        for (int j2 = 0; j2 < 4; j2++) {
            const int rb = j2 & 1;
            const int ja = 2 * j2, jb = 2 * j2 + 1;

            float2 nb1 = sEO[rb][i + 1];      // (E_{i-1}, O_{i-1}) at t-1
            float2 nb0 = sEO[rb][i];          // .y = O_{i-2} at t-1

            // off-chain: prefetch emissions for steps (+8)
            {
                int ta = t + ja + 8; if (ta > steps) ta = steps;
                const float* p = rowp + (size_t)ta * C;
                float a0 = __ldg(p) * LOG2E;
                float a1 = __ldg(p + lbl) * LOG2E;
                float a2 = __ldg(p + colm1) * LOG2E;
                int tb = t + jb + 8; if (tb > steps) tb = steps;
                const float* q = rowp + (size_t)tb * C;
                float b0 = __ldg(q) * LOG2E;
                float b1 = __ldg(q + lbl) * LOG2E;
                float b2 = __ldg(q + colm1) * LOG2E;
                // E2 step A (uses old O, off-chain)
                float E2a = lse2(E2, O) + eb[ja];

                float Om1 = nb1.y, Em1 = nb1.x, Om2 = nb0.y;
                // ---- step A ----
                float Ea   = lse2(E, Om1) + eb[ja];
                float Oa   = lse3(O, E, skip ? Om1 : NEGF) + el[ja];
                float Om1a = lse3(Om1, Em1, skipm1 ? Om2 : NEGF) + em[ja];
                // ---- step B ----
                float Eb = lse2(Ea, Om1a) + eb[jb];
                float Ob = lse3(Oa, Ea, skip ? Om1a : NEGF) + el[jb];

                if (i == 127) E2 = lse2(E2a, Oa) + eb[jb];   // step B of E2

                sEO[rb ^ 1][i + 2] = make_float2(Eb, Ob);
                E = Eb; O = Ob;
                eb[ja] = a0; el[ja] = a1; em[ja] = a2;
                eb[jb] = b0; el[jb] = b1; em[jb] = b2;
            }
            __syncthreads();
        }
    }
    // ---- tail: single-step rounds (< 8 remaining) ----
    {
        int rb = 0;
        for (; t <= steps; t++) {
            const float* p = rowp + (size_t)t * C;
            float ebx = __ldg(p) * LOG2E;
            float elx = __ldg(p + lbl) * LOG2E;

            float Om1 = sEO[rb][i + 1].y;
            if (i == 127) E2 = lse2(E2, O) + ebx;
            float nE = lse2(E, Om1) + ebx;
            float nO = lse3(O, E, skip ? Om1 : NEGF) + elx;
            sEO[rb ^ 1][i + 2] = make_float2(nE, nO);
            E = nE; O = nO;
            rb ^= 1;
            __syncthreads();
        }
    }

    // ---- gather + per-example loss ----
    sOf[i] = O;
    sEf[i] = E;
    if (i == 127) sEf[128] = E2;
    __syncthreads();

    if (i == 0) {
        int tl = target_lengths[b];
        int tlc = tl; if (tlc < 1) tlc = 1; if (tlc > L) tlc = L;
        float l1 = sOf[tlc - 1];        // state 2*tl - 1
        float l2 = sEf[tlc];            // state 2*tl
        float per = -(lse2(l1, l2) * LN2);
        if (per > 1e29f) per = 0.0f;
        int denom = tl < 1 ? 1 : tl;
        g_per_ex[b] = per / (float)denom;
        __threadfence();
        unsigned prevc = atomicAdd(&g_count, 1u);
        s_last = (prevc == (unsigned)(B - 1)) ? 1u : 0u;
    }
    __syncthreads();

    // ---- last block computes the batch mean (deterministic fixed order) ----
    if (s_last) {
        float v = 0.f;
        for (int idx = i; idx < B; idx += 128)
            v += *((volatile float*)&g_per_ex[idx]);
#pragma unroll
        for (int o = 16; o > 0; o >>= 1)
            v += __shfl_down_sync(0xffffffffu, v, o);
        if (lane == 0) sred[w] = v;
        __syncthreads();
        if (i == 0) {
            float tot = sred[0] + sred[1] + sred[2] + sred[3];
            out[0] = tot / (float)B;
            g_count = 0;    // reset for next graph replay
        }
    }
}

extern "C" void kernel_launch(void* const* d_in, const int* in_sizes, int n_in,
                              void* d_out, int out_size)
{
    const float* pred           = (const float*)d_in[0];
    const int*   targets        = (const int*)d_in[1];
    const int*   pred_lengths   = (const int*)d_in[2];
    const int*   target_lengths = (const int*)d_in[3];

    const int B = in_sizes[2];
    const int L = in_sizes[1] / B;
    const int C = 128;
    const int T = (in_sizes[0] / B) / C;

    ctc_forward_kernel<<<B, 128>>>(pred, targets, pred_lengths, target_lengths,
                                   (float*)d_out, T, C, L, B);
}